// round 3
// baseline (speedup 1.0000x reference)
#include <cuda_runtime.h>
#include <cuda_bf16.h>

#define NUM_C 46
#define TILE_ROWS 64
#define TILE_FLOATS (TILE_ROWS * NUM_C)   // 2944
#define TILE_VEC (TILE_FLOATS / 4)        // 736
#define THREADS 256
#define BLOCKS 592                        // 4 per SM on 148 SMs

__device__ float g_col[NUM_C];
__device__ float g_tp[NUM_C];
__device__ float g_cnt[NUM_C];

__global__ void zero_kernel() {
    int t = threadIdx.x;
    if (t < NUM_C) {
        g_col[t] = 0.0f;
        g_tp[t]  = 0.0f;
        g_cnt[t] = 0.0f;
    }
}

__global__ __launch_bounds__(THREADS) void accum_kernel(
    const float* __restrict__ y_pred,
    const int* __restrict__ y_true,
    int n_rows)
{
    __shared__ float s_tile[TILE_FLOATS];
    __shared__ float s_tp[NUM_C];
    __shared__ float s_cnt[NUM_C];
    __shared__ float s_col[NUM_C];

    const int t = threadIdx.x;
    if (t < NUM_C) {
        s_tp[t]  = 0.0f;
        s_cnt[t] = 0.0f;
        s_col[t] = 0.0f;
    }
    __syncthreads();

    // compute-thread mapping: 230 active threads, c = class, g = row-group (0..4)
    const int c = t % NUM_C;
    const int g = t / NUM_C;          // 0..5 ; g<5 means active (t<230)
    float acc = 0.0f;

    const int num_tiles = (n_rows + TILE_ROWS - 1) / TILE_ROWS;

    for (int tile = blockIdx.x; tile < num_tiles; tile += gridDim.x) {
        const int row0 = tile * TILE_ROWS;
        const int rows_here = min(TILE_ROWS, n_rows - row0);

        if (rows_here == TILE_ROWS) {
            // fully aligned fast path: row0 multiple of 64 -> byte offset multiple of 16
            const float4* src = reinterpret_cast<const float4*>(y_pred) +
                                (size_t)row0 * NUM_C / 4;
            float4* dst = reinterpret_cast<float4*>(s_tile);
            #pragma unroll
            for (int i = t; i < TILE_VEC; i += THREADS)
                dst[i] = src[i];
        } else {
            const int n_elem = rows_here * NUM_C;
            for (int i = t; i < n_elem; i += THREADS)
                s_tile[i] = y_pred[(size_t)row0 * NUM_C + i];
        }
        __syncthreads();

        // column partial sums into a single register each
        if (g < 5) {
            for (int r = g; r < rows_here; r += 5)
                acc += s_tile[r * NUM_C + c];
        }

        // tp / counts : one contribution per row
        if (t < rows_here) {
            const int lab = y_true[row0 + t];
            atomicAdd(&s_tp[lab], s_tile[t * NUM_C + lab]);
            atomicAdd(&s_cnt[lab], 1.0f);
        }
        __syncthreads();
    }

    // flush per-thread accumulators
    if (g < 5)
        atomicAdd(&s_col[c], acc);
    __syncthreads();

    if (t < NUM_C) {
        atomicAdd(&g_col[t], s_col[t]);
        atomicAdd(&g_tp[t],  s_tp[t]);
        atomicAdd(&g_cnt[t], s_cnt[t]);
    }
}

__global__ void finalize_kernel(float* __restrict__ out) {
    __shared__ float s_f1[NUM_C];
    const float EPS = 1e-7f;
    int t = threadIdx.x;
    if (t < NUM_C) {
        float tp      = g_tp[t];
        float col_sum = g_col[t];   // tp + fp
        float cnt     = g_cnt[t];   // tp + fn
        float precision = tp / (col_sum + EPS);
        float recall    = tp / (cnt + EPS);
        float f1 = 2.0f * precision * recall / (precision + recall + EPS);
        f1 = fminf(fmaxf(f1, EPS), 1.0f - EPS);
        s_f1[t] = f1;
    }
    __syncthreads();
    if (t == 0) {
        float s = 0.0f;
        #pragma unroll
        for (int i = 0; i < NUM_C; i++) s += s_f1[i];
        out[0] = 1.0f - s / (float)NUM_C;
    }
}

extern "C" void kernel_launch(void* const* d_in, const int* in_sizes, int n_in,
                              void* d_out, int out_size) {
    const float* y_pred = (const float*)d_in[0];
    const int*   y_true = (const int*)d_in[1];
    float* out = (float*)d_out;

    const int n_rows = in_sizes[0] / NUM_C;   // derive from y_pred element count

    zero_kernel<<<1, 64>>>();
    accum_kernel<<<BLOCKS, THREADS>>>(y_pred, y_true, n_rows);
    finalize_kernel<<<1, 64>>>(out);
}

// round 4
// speedup vs baseline: 1.9635x; 1.9635x over previous
#include <cuda_runtime.h>
#include <cuda_bf16.h>
#include <cstdint>

#define NUM_C 46
#define TILE_ROWS 64
#define TILE_FLOATS (TILE_ROWS * NUM_C)   // 2944
#define TILE_VEC (TILE_FLOATS / 4)        // 736
#define THREADS 256
#define BLOCKS 1184                       // 8 per SM on 148 SMs
#define NPART (3 * NUM_C)                 // 138: [col | tp | cnt]

__device__ float g_part[BLOCKS][NPART];

__device__ __forceinline__ void cp_async16(void* smem, const void* gmem) {
    uint32_t s = (uint32_t)__cvta_generic_to_shared(smem);
    asm volatile("cp.async.cg.shared.global [%0], [%1], 16;\n" :: "r"(s), "l"(gmem));
}
__device__ __forceinline__ void cp_async4(void* smem, const void* gmem) {
    uint32_t s = (uint32_t)__cvta_generic_to_shared(smem);
    asm volatile("cp.async.ca.shared.global [%0], [%1], 4;\n" :: "r"(s), "l"(gmem));
}
#define CP_COMMIT() asm volatile("cp.async.commit_group;\n" ::: "memory")
#define CP_WAIT(n)  asm volatile("cp.async.wait_group %0;\n" :: "n"(n) : "memory")

__global__ __launch_bounds__(THREADS) void accum_kernel(
    const float* __restrict__ y_pred,
    const int* __restrict__ y_true,
    int n_rows)
{
    __shared__ float s_tile[2][TILE_FLOATS];
    __shared__ float s_tp[NUM_C];
    __shared__ float s_cnt[NUM_C];
    __shared__ float s_col[NUM_C];

    const int t = threadIdx.x;
    if (t < NUM_C) {
        s_tp[t]  = 0.0f;
        s_cnt[t] = 0.0f;
        s_col[t] = 0.0f;
    }

    const int c = t % NUM_C;
    const int g = t / NUM_C;          // 0..5 ; g<5 means active (t<230)
    float acc = 0.0f;

    const int num_tiles = (n_rows + TILE_ROWS - 1) / TILE_ROWS;

    // issue async loads for one tile into buffer b (all threads must call:
    // commit_group is per-thread, empty groups are fine)
    auto issue = [&](int tile_idx, int b) {
        const int row0 = tile_idx * TILE_ROWS;
        const int rows = min(TILE_ROWS, n_rows - row0);
        if (rows == TILE_ROWS) {
            const float4* src = reinterpret_cast<const float4*>(y_pred) +
                                (size_t)row0 * NUM_C / 4;
            float4* dst = reinterpret_cast<float4*>(s_tile[b]);
            #pragma unroll
            for (int i = t; i < TILE_VEC; i += THREADS)
                cp_async16(&dst[i], &src[i]);
        } else {
            const int n_el = rows * NUM_C;
            const float* src = y_pred + (size_t)row0 * NUM_C;
            for (int i = t; i < n_el; i += THREADS)
                cp_async4(&s_tile[b][i], &src[i]);
        }
        CP_COMMIT();
    };

    int tile = blockIdx.x;
    if (tile < num_tiles) issue(tile, 0);
    __syncthreads();   // also covers the s_* zero-init above

    int b = 0;
    for (; tile < num_tiles; tile += gridDim.x) {
        const int nxt = tile + gridDim.x;
        if (nxt < num_tiles) {
            issue(nxt, b ^ 1);
            CP_WAIT(1);          // tile 'tile' complete, 'nxt' may be in flight
        } else {
            CP_WAIT(0);
        }
        __syncthreads();         // make other threads' copies visible

        const int row0 = tile * TILE_ROWS;
        const int rows_here = min(TILE_ROWS, n_rows - row0);
        const float* tl = s_tile[b];

        // column partial sums into a single register each
        if (g < 5) {
            if (rows_here == TILE_ROWS) {
                #pragma unroll
                for (int r = 0; r < TILE_ROWS; r += 5) {
                    int rr = r + g;
                    if (rr < TILE_ROWS) acc += tl[rr * NUM_C + c];
                }
            } else {
                for (int r = g; r < rows_here; r += 5)
                    acc += tl[r * NUM_C + c];
            }
        }

        // tp / counts : one contribution per row
        if (t < rows_here) {
            const int lab = y_true[row0 + t];
            atomicAdd(&s_tp[lab], tl[t * NUM_C + lab]);
            atomicAdd(&s_cnt[lab], 1.0f);
        }
        __syncthreads();         // buf b safe to overwrite at tile+2
        b ^= 1;
    }

    // flush per-thread accumulators
    if (g < 5)
        atomicAdd(&s_col[c], acc);
    __syncthreads();

    if (t < NPART) {
        float v = (t < NUM_C) ? s_col[t]
                : (t < 2 * NUM_C) ? s_tp[t - NUM_C]
                : s_cnt[t - 2 * NUM_C];
        g_part[blockIdx.x][t] = v;
    }
}

__global__ __launch_bounds__(1024) void finalize_kernel(float* __restrict__ out) {
    __shared__ float s_sum[NPART];
    __shared__ float s_f1[NUM_C];
    const float EPS = 1e-7f;
    const int t = threadIdx.x;

    if (t < NPART) s_sum[t] = 0.0f;
    __syncthreads();

    const int j = t % NPART;     // which partial
    const int s = t / NPART;     // slice 0..6 active (7*138=966)
    if (s < 7) {
        float a = 0.0f;
        for (int bk = s; bk < BLOCKS; bk += 7)
            a += g_part[bk][j];
        atomicAdd(&s_sum[j], a);
    }
    __syncthreads();

    if (t < NUM_C) {
        float col_sum = s_sum[t];                // tp + fp
        float tp      = s_sum[NUM_C + t];
        float cnt     = s_sum[2 * NUM_C + t];    // tp + fn
        float precision = tp / (col_sum + EPS);
        float recall    = tp / (cnt + EPS);
        float f1 = 2.0f * precision * recall / (precision + recall + EPS);
        f1 = fminf(fmaxf(f1, EPS), 1.0f - EPS);
        s_f1[t] = f1;
    }
    __syncthreads();
    if (t == 0) {
        float sm = 0.0f;
        #pragma unroll
        for (int i = 0; i < NUM_C; i++) sm += s_f1[i];
        out[0] = 1.0f - sm / (float)NUM_C;
    }
}

extern "C" void kernel_launch(void* const* d_in, const int* in_sizes, int n_in,
                              void* d_out, int out_size) {
    const float* y_pred = (const float*)d_in[0];
    const int*   y_true = (const int*)d_in[1];
    float* out = (float*)d_out;

    const int n_rows = in_sizes[0] / NUM_C;   // derive from y_pred element count

    accum_kernel<<<BLOCKS, THREADS>>>(y_pred, y_true, n_rows);
    finalize_kernel<<<1, 1024>>>(out);
}

// round 9
// speedup vs baseline: 2.1520x; 1.0960x over previous
#include <cuda_runtime.h>
#include <cuda_bf16.h>
#include <cstdint>

#define NUM_C 46
#define TILE_ROWS 64
#define TILE_FLOATS (TILE_ROWS * NUM_C)   // 2944
#define TILE_VEC (TILE_FLOATS / 4)        // 736
#define THREADS 256
#define BLOCKS 1184                       // 8 per SM on 148 SMs
#define NPART (3 * NUM_C)                 // 138: [col | tp | cnt]

__device__ float g_sum[NPART];            // zero-initialized at load; each launch restores it
__device__ unsigned int g_ticket = 0;

__device__ __forceinline__ void cp_async16(void* smem, const void* gmem) {
    uint32_t s = (uint32_t)__cvta_generic_to_shared(smem);
    asm volatile("cp.async.cg.shared.global [%0], [%1], 16;\n" :: "r"(s), "l"(gmem));
}
__device__ __forceinline__ void cp_async4(void* smem, const void* gmem) {
    uint32_t s = (uint32_t)__cvta_generic_to_shared(smem);
    asm volatile("cp.async.ca.shared.global [%0], [%1], 4;\n" :: "r"(s), "l"(gmem));
}
#define CP_COMMIT() asm volatile("cp.async.commit_group;\n" ::: "memory")
#define CP_WAIT(n)  asm volatile("cp.async.wait_group %0;\n" :: "n"(n) : "memory")

__global__ __launch_bounds__(THREADS) void accum_kernel(
    const float* __restrict__ y_pred,
    const int* __restrict__ y_true,
    int n_rows,
    float* __restrict__ out)
{
    __shared__ float s_tile[2][TILE_FLOATS];
    __shared__ float s_tp[NUM_C];
    __shared__ float s_cnt[NUM_C];
    __shared__ float s_col[NUM_C];
    __shared__ unsigned int s_rank;

    const int t = threadIdx.x;
    if (t < NUM_C) {
        s_tp[t]  = 0.0f;
        s_cnt[t] = 0.0f;
        s_col[t] = 0.0f;
    }

    const int c = t % NUM_C;
    const int g = t / NUM_C;          // 0..5 ; g<5 means active (t<230)
    float acc = 0.0f;

    const int num_tiles = (n_rows + TILE_ROWS - 1) / TILE_ROWS;

    auto issue = [&](int tile_idx, int b) {
        const int row0 = tile_idx * TILE_ROWS;
        const int rows = min(TILE_ROWS, n_rows - row0);
        if (rows == TILE_ROWS) {
            const float4* src = reinterpret_cast<const float4*>(y_pred) +
                                (size_t)row0 * NUM_C / 4;
            float4* dst = reinterpret_cast<float4*>(s_tile[b]);
            #pragma unroll
            for (int i = t; i < TILE_VEC; i += THREADS)
                cp_async16(&dst[i], &src[i]);
        } else {
            const int n_el = rows * NUM_C;
            const float* src = y_pred + (size_t)row0 * NUM_C;
            for (int i = t; i < n_el; i += THREADS)
                cp_async4(&s_tile[b][i], &src[i]);
        }
        CP_COMMIT();
    };

    int tile = blockIdx.x;
    if (tile < num_tiles) issue(tile, 0);
    __syncthreads();   // covers the s_* zero-init above too

    int b = 0;
    for (; tile < num_tiles; tile += gridDim.x) {
        const int nxt = tile + gridDim.x;
        if (nxt < num_tiles) {
            issue(nxt, b ^ 1);
            CP_WAIT(1);          // current tile complete, next may be in flight
        } else {
            CP_WAIT(0);
        }
        __syncthreads();

        const int row0 = tile * TILE_ROWS;
        const int rows_here = min(TILE_ROWS, n_rows - row0);
        const float* tl = s_tile[b];

        if (g < 5) {
            if (rows_here == TILE_ROWS) {
                #pragma unroll
                for (int r = 0; r < TILE_ROWS; r += 5) {
                    int rr = r + g;
                    if (rr < TILE_ROWS) acc += tl[rr * NUM_C + c];
                }
            } else {
                for (int r = g; r < rows_here; r += 5)
                    acc += tl[r * NUM_C + c];
            }
        }

        if (t < rows_here) {
            const int lab = y_true[row0 + t];
            atomicAdd(&s_tp[lab], tl[t * NUM_C + lab]);
            atomicAdd(&s_cnt[lab], 1.0f);
        }
        __syncthreads();
        b ^= 1;
    }

    // flush per-thread accumulators to shared
    if (g < 5)
        atomicAdd(&s_col[c], acc);
    __syncthreads();

    // flush block partials straight to the global accumulators
    if (t < NPART) {
        float v = (t < NUM_C) ? s_col[t]
                : (t < 2 * NUM_C) ? s_tp[t - NUM_C]
                : s_cnt[t - 2 * NUM_C];
        atomicAdd(&g_sum[t], v);
    }
    __threadfence();
    __syncthreads();

    if (t == 0)
        s_rank = atomicAdd(&g_ticket, 1u);
    __syncthreads();

    if (s_rank == (unsigned)(gridDim.x - 1)) {
        // last block: all other blocks' atomics are globally visible
        __shared__ float s_f1[NUM_C];
        const float EPS = 1e-7f;
        volatile float* gs = g_sum;
        if (t < NUM_C) {
            float col_sum = gs[t];                // tp + fp
            float tp      = gs[NUM_C + t];
            float cnt     = gs[2 * NUM_C + t];    // tp + fn
            float precision = tp / (col_sum + EPS);
            float recall    = tp / (cnt + EPS);
            float f1 = 2.0f * precision * recall / (precision + recall + EPS);
            f1 = fminf(fmaxf(f1, EPS), 1.0f - EPS);
            s_f1[t] = f1;
        }
        __syncthreads();
        if (t == 0) {
            float sm = 0.0f;
            #pragma unroll
            for (int i = 0; i < NUM_C; i++) sm += s_f1[i];
            out[0] = 1.0f - sm / (float)NUM_C;
        }
        __syncthreads();
        // restore state for the next (graph-replayed) launch
        if (t < NPART) g_sum[t] = 0.0f;
        if (t == 0) g_ticket = 0u;
        __threadfence();
    }
}

extern "C" void kernel_launch(void* const* d_in, const int* in_sizes, int n_in,
                              void* d_out, int out_size) {
    const float* y_pred = (const float*)d_in[0];
    const int*   y_true = (const int*)d_in[1];
    float* out = (float*)d_out;

    const int n_rows = in_sizes[0] / NUM_C;   // derive from y_pred element count

    accum_kernel<<<BLOCKS, THREADS>>>(y_pred, y_true, n_rows, out);
}

// round 10
// speedup vs baseline: 2.2405x; 1.0411x over previous
#include <cuda_runtime.h>
#include <cuda_bf16.h>
#include <cstdint>

#define NUM_C 46
#define WARPS 8
#define THREADS (WARPS * 32)
#define WARP_ROWS 16
#define WTILE_FLOATS (WARP_ROWS * NUM_C)   // 736
#define WTILE_VEC (WTILE_FLOATS / 4)       // 184
#define BLOCKS 592                         // 4 per SM on 148 SMs (smem-limited)
#define NPART (3 * NUM_C)                  // 138: [col | tp | cnt]

__device__ float g_sum[NPART];             // zeroed at load; each launch restores it
__device__ unsigned int g_ticket = 0;

__device__ __forceinline__ void cp_async16(void* smem, const void* gmem) {
    uint32_t s = (uint32_t)__cvta_generic_to_shared(smem);
    asm volatile("cp.async.cg.shared.global [%0], [%1], 16;\n" :: "r"(s), "l"(gmem));
}
__device__ __forceinline__ void cp_async4(void* smem, const void* gmem) {
    uint32_t s = (uint32_t)__cvta_generic_to_shared(smem);
    asm volatile("cp.async.ca.shared.global [%0], [%1], 4;\n" :: "r"(s), "l"(gmem));
}
#define CP_COMMIT() asm volatile("cp.async.commit_group;\n" ::: "memory")
#define CP_WAIT(n)  asm volatile("cp.async.wait_group %0;\n" :: "n"(n) : "memory")

__global__ __launch_bounds__(THREADS) void accum_kernel(
    const float* __restrict__ y_pred,
    const int* __restrict__ y_true,
    int n_rows,
    float* __restrict__ out)
{
    __shared__ float s_buf[WARPS][2][WTILE_FLOATS];   // 47104 B
    __shared__ float s_tp[NUM_C];
    __shared__ float s_cnt[NUM_C];
    __shared__ float s_col[NUM_C];
    __shared__ unsigned int s_rank;

    const int t    = threadIdx.x;
    const int wid  = t >> 5;
    const int lane = t & 31;

    if (t < NUM_C) {
        s_tp[t]  = 0.0f;
        s_cnt[t] = 0.0f;
        s_col[t] = 0.0f;
    }

    const int num_wt  = (n_rows + WARP_ROWS - 1) / WARP_ROWS;
    const int wstride = gridDim.x * WARPS;

    // per-warp async copy of one 16-row tile into buffer b
    auto issue = [&](int wt, int b) {
        const int row0 = wt * WARP_ROWS;
        const int rows = min(WARP_ROWS, n_rows - row0);
        if (rows == WARP_ROWS) {
            const float4* src = reinterpret_cast<const float4*>(y_pred) +
                                (size_t)row0 * NUM_C / 4;
            float4* dst = reinterpret_cast<float4*>(s_buf[wid][b]);
            #pragma unroll
            for (int i = lane; i < WTILE_VEC; i += 32)
                cp_async16(&dst[i], &src[i]);
        } else {
            const int n_el = rows * NUM_C;
            const float* src = y_pred + (size_t)row0 * NUM_C;
            for (int i = lane; i < n_el; i += 32)
                cp_async4(&s_buf[wid][b][i], &src[i]);
        }
        CP_COMMIT();
    };

    int wt = blockIdx.x * WARPS + wid;
    if (wt < num_wt) issue(wt, 0);
    __syncthreads();       // one-time: covers s_tp/s_cnt/s_col zero-init

    float acc0 = 0.0f;     // class = lane        (0..31)
    float acc1 = 0.0f;     // class = 32 + lane   (lanes 0..13)

    int b = 0;
    for (; wt < num_wt; wt += wstride) {
        const int nxt = wt + wstride;
        if (nxt < num_wt) {
            issue(nxt, b ^ 1);
            CP_WAIT(1);          // current tile arrived; next may be in flight
        } else {
            CP_WAIT(0);
        }
        __syncwarp();            // all lanes' copies for this tile complete

        const int row0 = wt * WARP_ROWS;
        const int rows_here = min(WARP_ROWS, n_rows - row0);
        const float* tl = s_buf[wid][b];

        if (rows_here == WARP_ROWS) {
            #pragma unroll
            for (int r = 0; r < WARP_ROWS; r++) {
                acc0 += tl[r * NUM_C + lane];
                if (lane < NUM_C - 32)
                    acc1 += tl[r * NUM_C + 32 + lane];
            }
        } else {
            for (int r = 0; r < rows_here; r++) {
                acc0 += tl[r * NUM_C + lane];
                if (lane < NUM_C - 32)
                    acc1 += tl[r * NUM_C + 32 + lane];
            }
        }

        if (lane < rows_here) {
            const int lab = y_true[row0 + lane];
            atomicAdd(&s_tp[lab], tl[lane * NUM_C + lab]);
            atomicAdd(&s_cnt[lab], 1.0f);
        }
        __syncwarp();
        b ^= 1;
    }

    // flush per-lane class accumulators (8 warps contend lightly per class)
    atomicAdd(&s_col[lane], acc0);
    if (lane < NUM_C - 32)
        atomicAdd(&s_col[32 + lane], acc1);
    __syncthreads();

    // flush block partials straight to the global accumulators
    if (t < NPART) {
        float v = (t < NUM_C) ? s_col[t]
                : (t < 2 * NUM_C) ? s_tp[t - NUM_C]
                : s_cnt[t - 2 * NUM_C];
        atomicAdd(&g_sum[t], v);
    }
    __threadfence();
    __syncthreads();

    if (t == 0)
        s_rank = atomicAdd(&g_ticket, 1u);
    __syncthreads();

    if (s_rank == (unsigned)(gridDim.x - 1)) {
        // last block: all other blocks' atomics are globally visible
        __shared__ float s_f1[NUM_C];
        const float EPS = 1e-7f;
        volatile float* gs = g_sum;
        if (t < NUM_C) {
            float col_sum = gs[t];                // tp + fp
            float tp      = gs[NUM_C + t];
            float cnt     = gs[2 * NUM_C + t];    // tp + fn
            float precision = tp / (col_sum + EPS);
            float recall    = tp / (cnt + EPS);
            float f1 = 2.0f * precision * recall / (precision + recall + EPS);
            f1 = fminf(fmaxf(f1, EPS), 1.0f - EPS);
            s_f1[t] = f1;
        }
        __syncthreads();
        if (t == 0) {
            float sm = 0.0f;
            #pragma unroll
            for (int i = 0; i < NUM_C; i++) sm += s_f1[i];
            out[0] = 1.0f - sm / (float)NUM_C;
        }
        __syncthreads();
        // restore state for the next (graph-replayed) launch
        if (t < NPART) g_sum[t] = 0.0f;
        if (t == 0) g_ticket = 0u;
        __threadfence();
    }
}

extern "C" void kernel_launch(void* const* d_in, const int* in_sizes, int n_in,
                              void* d_out, int out_size) {
    const float* y_pred = (const float*)d_in[0];
    const int*   y_true = (const int*)d_in[1];
    float* out = (float*)d_out;

    const int n_rows = in_sizes[0] / NUM_C;   // derive from y_pred element count

    accum_kernel<<<BLOCKS, THREADS>>>(y_pred, y_true, n_rows, out);
}